// round 3
// baseline (speedup 1.0000x reference)
#include <cuda_runtime.h>
#include <math.h>

#define H 224
#define R 56
#define KE 280          // width of E = [A | C]
#define NTHR 256
#define TS 112          // GEMM tile
#define BK 28           // GEMM k-chunk

// KW smem strides (floats)
#define SU  228
#define STT 60
#define SMM 57
#define SXS 36
#define SCC 60

__device__ float g_D[H * H];                 // DCT-II matrix, g_D[k*H+i]
__device__ float g_E[H * KE];                // E = [A | C], A = D^2, C = D[:, :56]
__device__ float g_Z[1536L * H * KE];        // per-image Z = [A X | -C(U X U^T)]

// ---------------------------------------------------------------- init D
__global__ void init_D_kernel() {
    int idx = blockIdx.x * blockDim.x + threadIdx.x;
    if (idx >= H * H) return;
    int k = idx / H;
    int i = idx - k * H;
    double v = cos(3.14159265358979323846 * (2.0 * i + 1.0) * (double)k / (2.0 * H))
             * sqrt(2.0 / (double)H);
    if (k == 0) v *= 0.70710678118654752440;
    g_D[idx] = (float)v;
}

// ---------------------------------------------------------------- init E
// block j computes row j of E: E[j][c<224] = (D^2)[j][c], E[j][224+k] = D[j][k]
__global__ void init_E_kernel() {
    __shared__ float sDj[H];
    int j = blockIdx.x;
    for (int k = threadIdx.x; k < H; k += blockDim.x) sDj[k] = g_D[j * H + k];
    __syncthreads();
    for (int c = threadIdx.x; c < KE; c += blockDim.x) {
        if (c < H) {
            float s = 0.f;
            for (int k = 0; k < H; k++) s += sDj[k] * g_D[k * H + c];
            g_E[j * KE + c] = s;
        } else {
            g_E[j * KE + c] = sDj[c - H];
        }
    }
}

// ---------------------------------------------------------------- KW
// per image: t = X U^T (224x56), M = U t (56x56), W = C M (224x56);
// writes -W into g_Z[img] columns 224..279.
__global__ __launch_bounds__(NTHR, 1)
void kw_kernel(const float* __restrict__ x) {
    extern __shared__ float smem[];
    float* sU = smem;                  // R*SU   : U[l][w]
    float* sT = sU + R * SU;           // H*STT  : t[h][l]
    float* sM = sT + H * STT;          // R*SMM  : M[k][l]
    float* sX = sM + R * SMM;          // H*SXS  : 32-col chunk of X
    float* sC = sX + H * SXS;          // H*SCC  : C[i][k] = D[i][k], k<56

    const int tid = threadIdx.x;
    const int wp  = tid >> 5;
    const int ln  = tid & 31;
    const long imgbase = (long)blockIdx.x * (H * H);
    const float* __restrict__ xi = x + imgbase;

    // load U (rows 0..55 of D) and C (cols 0..55 of D)
    for (int idx = tid; idx < R * H; idx += NTHR) {
        int k = idx / H;
        int w = idx - k * H;
        sU[k * SU + w] = g_D[idx];
    }
    for (int idx = tid; idx < H * R; idx += NTHR) {
        int i = idx / R;
        int k = idx - i * R;
        sC[i * SCC + k] = g_D[i * H + k];
    }
    __syncthreads();

    // ---- stage 1: t[h][l] = sum_w X[h][w] * U[l][w] ----
    const int l0 = wp * 7;
    float acc[7][7];
#pragma unroll
    for (int a = 0; a < 7; a++)
#pragma unroll
        for (int b = 0; b < 7; b++) acc[a][b] = 0.f;

#pragma unroll 1
    for (int c = 0; c < 7; c++) {
        const int w0 = c * 32;
#pragma unroll
        for (int p = 0; p < 7; p++) {
            int row = (tid >> 3) + 32 * p;
            int cv  = (tid & 7) * 4;
            float4 v = *reinterpret_cast<const float4*>(&xi[row * H + w0 + cv]);
            *reinterpret_cast<float4*>(&sX[row * SXS + cv]) = v;
        }
        __syncthreads();
#pragma unroll 1
        for (int w4 = 0; w4 < 8; w4++) {
            const int wl = w4 * 4;
            float4 xv[7];
#pragma unroll
            for (int hi = 0; hi < 7; hi++)
                xv[hi] = *reinterpret_cast<const float4*>(&sX[(ln + 32 * hi) * SXS + wl]);
#pragma unroll
            for (int li = 0; li < 7; li++) {
                float4 u = *reinterpret_cast<const float4*>(&sU[(l0 + li) * SU + w0 + wl]);
#pragma unroll
                for (int hi = 0; hi < 7; hi++) {
                    acc[li][hi] += u.x * xv[hi].x;
                    acc[li][hi] += u.y * xv[hi].y;
                    acc[li][hi] += u.z * xv[hi].z;
                    acc[li][hi] += u.w * xv[hi].w;
                }
            }
        }
        __syncthreads();
    }
#pragma unroll
    for (int li = 0; li < 7; li++)
#pragma unroll
        for (int hi = 0; hi < 7; hi++)
            sT[(ln + 32 * hi) * STT + l0 + li] = acc[li][hi];
    __syncthreads();

    // ---- stage 2: M[k][l] = sum_h U[k][h] * t[h][l] ----
    {
        const int k0 = wp * 7;
        float a0[7], a1[7];
#pragma unroll
        for (int ki = 0; ki < 7; ki++) { a0[ki] = 0.f; a1[ki] = 0.f; }
#pragma unroll 1
        for (int h4 = 0; h4 < 56; h4++) {
            const int h = h4 * 4;
            float4 u[7];
#pragma unroll
            for (int ki = 0; ki < 7; ki++)
                u[ki] = *reinterpret_cast<const float4*>(&sU[(k0 + ki) * SU + h]);
            const float* up = reinterpret_cast<const float*>(u);
#pragma unroll
            for (int dh = 0; dh < 4; dh++) {
                float t0 = sT[(h + dh) * STT + ln];
                float t1 = (ln < 24) ? sT[(h + dh) * STT + 32 + ln] : 0.f;
#pragma unroll
                for (int ki = 0; ki < 7; ki++) {
                    float uv = up[ki * 4 + dh];
                    a0[ki] += uv * t0;
                    a1[ki] += uv * t1;
                }
            }
        }
#pragma unroll
        for (int ki = 0; ki < 7; ki++) {
            sM[(k0 + ki) * SMM + ln] = a0[ki];
            if (ln < 24) sM[(k0 + ki) * SMM + 32 + ln] = a1[ki];
        }
    }
    __syncthreads();

    // ---- stage 3: W[i][l] = sum_k C[i][k] * M[k][l]; write -W to g_Z ----
    float* zi = g_Z + (long)blockIdx.x * (H * KE);
#pragma unroll 1
    for (int it = 0; it < 4; it++) {
        const int i0 = wp * 28 + it * 7;
        float a0[7], a1[7];
#pragma unroll
        for (int ii = 0; ii < 7; ii++) { a0[ii] = 0.f; a1[ii] = 0.f; }
#pragma unroll 1
        for (int k4 = 0; k4 < 14; k4++) {
            const int k = k4 * 4;
            float4 u[7];
#pragma unroll
            for (int ii = 0; ii < 7; ii++)
                u[ii] = *reinterpret_cast<const float4*>(&sC[(i0 + ii) * SCC + k]);
            const float* up = reinterpret_cast<const float*>(u);
#pragma unroll
            for (int dk = 0; dk < 4; dk++) {
                float m0 = sM[(k + dk) * SMM + ln];
                float m1 = (ln < 24) ? sM[(k + dk) * SMM + 32 + ln] : 0.f;
#pragma unroll
                for (int ii = 0; ii < 7; ii++) {
                    float uv = up[ii * 4 + dk];
                    a0[ii] += uv * m0;
                    a1[ii] += uv * m1;
                }
            }
        }
#pragma unroll
        for (int ii = 0; ii < 7; ii++) {
            zi[(i0 + ii) * KE + H + ln] = -a0[ii];
            if (ln < 24) zi[(i0 + ii) * KE + H + 32 + ln] = -a1[ii];
        }
    }
}

// ---------------------------------------------------------------- KY
// Y = A X per image (NN GEMM), Y -> g_Z columns 0..223
__global__ __launch_bounds__(NTHR, 2)
void ky_kernel(const float* __restrict__ x) {
    __shared__ float sA[TS * BK];        // A tile, [row][k], stride 28
    __shared__ float sB[BK * TS];        // X tile, [k][col], stride 112

    const int tid = threadIdx.x;
    const int ty = tid >> 4, tx = tid & 15;
    const int i0 = blockIdx.y * TS;
    const int w0 = blockIdx.x * TS;
    const long img = blockIdx.z;
    const float* __restrict__ xi = x + img * (H * H);
    float* zi = g_Z + img * (H * KE);

    float acc[7][7];
#pragma unroll
    for (int p = 0; p < 7; p++)
#pragma unroll
        for (int q = 0; q < 7; q++) acc[p][q] = 0.f;

#pragma unroll 1
    for (int kc = 0; kc < H; kc += BK) {
        for (int idx = tid; idx < TS * 7; idx += NTHR) {
            int row = idx / 7;
            int kv  = (idx - row * 7) * 4;
            float4 v = *reinterpret_cast<const float4*>(&g_E[(i0 + row) * KE + kc + kv]);
            *reinterpret_cast<float4*>(&sA[row * BK + kv]) = v;
        }
        for (int idx = tid; idx < BK * 28; idx += NTHR) {
            int kk = idx / 28;
            int cv = (idx - kk * 28) * 4;
            float4 v = *reinterpret_cast<const float4*>(&xi[(kc + kk) * H + w0 + cv]);
            *reinterpret_cast<float4*>(&sB[kk * TS + cv]) = v;
        }
        __syncthreads();
#pragma unroll
        for (int kk = 0; kk < BK; kk++) {
            float a[7], b[7];
#pragma unroll
            for (int p = 0; p < 7; p++) a[p] = sA[(ty * 7 + p) * BK + kk];
#pragma unroll
            for (int q = 0; q < 7; q++) b[q] = sB[kk * TS + tx * 7 + q];
#pragma unroll
            for (int p = 0; p < 7; p++)
#pragma unroll
                for (int q = 0; q < 7; q++) acc[p][q] += a[p] * b[q];
        }
        __syncthreads();
    }
#pragma unroll
    for (int p = 0; p < 7; p++)
#pragma unroll
        for (int q = 0; q < 7; q++)
            zi[(i0 + ty * 7 + p) * KE + w0 + tx * 7 + q] = acc[p][q];
}

// ---------------------------------------------------------------- KZ
// G = Z E^T (NT GEMM, k=280), out = x * G
#define SKP 29
__global__ __launch_bounds__(NTHR, 2)
void kz_kernel(const float* __restrict__ x, float* __restrict__ out) {
    __shared__ float sZ[TS * SKP];
    __shared__ float sE[TS * SKP];

    const int tid = threadIdx.x;
    const int ty = tid >> 4, tx = tid & 15;
    const int i0 = blockIdx.y * TS;
    const int j0 = blockIdx.x * TS;
    const long img = blockIdx.z;
    const float* __restrict__ xi = x + img * (H * H);
    float* oi = out + img * (H * H);
    const float* zi = g_Z + img * (H * KE);

    float acc[7][7];
#pragma unroll
    for (int p = 0; p < 7; p++)
#pragma unroll
        for (int q = 0; q < 7; q++) acc[p][q] = 0.f;

#pragma unroll 1
    for (int kc = 0; kc < KE; kc += BK) {
        for (int idx = tid; idx < TS * 7; idx += NTHR) {
            int row = idx / 7;
            int kv  = (idx - row * 7) * 4;
            float4 v = *reinterpret_cast<const float4*>(&zi[(i0 + row) * KE + kc + kv]);
            sZ[row * SKP + kv + 0] = v.x;
            sZ[row * SKP + kv + 1] = v.y;
            sZ[row * SKP + kv + 2] = v.z;
            sZ[row * SKP + kv + 3] = v.w;
            float4 e = *reinterpret_cast<const float4*>(&g_E[(j0 + row) * KE + kc + kv]);
            sE[row * SKP + kv + 0] = e.x;
            sE[row * SKP + kv + 1] = e.y;
            sE[row * SKP + kv + 2] = e.z;
            sE[row * SKP + kv + 3] = e.w;
        }
        __syncthreads();
#pragma unroll
        for (int kk = 0; kk < BK; kk++) {
            float a[7], b[7];
#pragma unroll
            for (int p = 0; p < 7; p++) a[p] = sZ[(ty * 7 + p) * SKP + kk];
#pragma unroll
            for (int q = 0; q < 7; q++) b[q] = sE[(tx * 7 + q) * SKP + kk];
#pragma unroll
            for (int p = 0; p < 7; p++)
#pragma unroll
                for (int q = 0; q < 7; q++) acc[p][q] += a[p] * b[q];
        }
        __syncthreads();
    }
#pragma unroll
    for (int p = 0; p < 7; p++) {
        int i = i0 + ty * 7 + p;
#pragma unroll
        for (int q = 0; q < 7; q++) {
            int j = j0 + tx * 7 + q;
            float xv = xi[i * H + j];
            oi[i * H + j] = xv * acc[p][q];
        }
    }
}

// ---------------------------------------------------------------- launch
extern "C" void kernel_launch(void* const* d_in, const int* in_sizes, int n_in,
                              void* d_out, int out_size) {
    const float* x = (const float*)d_in[0];
    float* out = (float*)d_out;
    const int nimg = out_size / (H * H);  // 1536

    init_D_kernel<<<(H * H + 255) / 256, 256>>>();
    init_E_kernel<<<H, 256>>>();

    const size_t smem_kw =
        (size_t)(R * SU + H * STT + R * SMM + H * SXS + H * SCC) * sizeof(float);
    static int cfg_done = 0;
    cudaFuncSetAttribute(kw_kernel, cudaFuncAttributeMaxDynamicSharedMemorySize,
                         (int)smem_kw);
    (void)cfg_done;

    kw_kernel<<<nimg, NTHR, smem_kw>>>(x);

    dim3 grid(2, 2, nimg);
    ky_kernel<<<grid, NTHR>>>(x);
    kz_kernel<<<grid, NTHR>>>(x, out);
}

// round 4
// speedup vs baseline: 1.0066x; 1.0066x over previous
#include <cuda_runtime.h>
#include <math.h>

#define H 224
#define R 56
#define KE 280          // width of E = [A | C]
#define NTHR 256
#define TS 112          // GEMM tile
#define BK 28           // GEMM k-chunk

// KW smem strides (floats)
#define SU  228
#define STT 60
#define SMM 57
#define SXS 36
#define SCC 60

__device__ float g_D[H * H];                 // DCT-II matrix, g_D[k*H+i]
__device__ float g_E[H * KE];                // E = [A | C], A = D^2, C = D[:, :56]
__device__ float g_Z[1536L * H * KE];        // per-image Z = [A X | -C(U X U^T)]

// ---------------------------------------------------------------- init D
__global__ void init_D_kernel() {
    int idx = blockIdx.x * blockDim.x + threadIdx.x;
    if (idx >= H * H) return;
    int k = idx / H;
    int i = idx - k * H;
    double v = cos(3.14159265358979323846 * (2.0 * i + 1.0) * (double)k / (2.0 * H))
             * sqrt(2.0 / (double)H);
    if (k == 0) v *= 0.70710678118654752440;
    g_D[idx] = (float)v;
}

// ---------------------------------------------------------------- init E
// block j computes row j of E: E[j][c<224] = (D^2)[j][c], E[j][224+k] = D[j][k]
__global__ void init_E_kernel() {
    __shared__ float sDj[H];
    int j = blockIdx.x;
    for (int k = threadIdx.x; k < H; k += blockDim.x) sDj[k] = g_D[j * H + k];
    __syncthreads();
    for (int c = threadIdx.x; c < KE; c += blockDim.x) {
        if (c < H) {
            float s = 0.f;
            for (int k = 0; k < H; k++) s += sDj[k] * g_D[k * H + c];
            g_E[j * KE + c] = s;
        } else {
            g_E[j * KE + c] = sDj[c - H];
        }
    }
}

// ---------------------------------------------------------------- KW
// per image: t = X U^T (224x56), M = U t (56x56), W = C M (224x56);
// writes -W into g_Z[img] columns 224..279.
__global__ __launch_bounds__(NTHR, 1)
void kw_kernel(const float* __restrict__ x) {
    extern __shared__ float smem[];
    float* sU = smem;                  // R*SU   : U[l][w]
    float* sT = sU + R * SU;           // H*STT  : t[h][l]
    float* sM = sT + H * STT;          // R*SMM  : M[k][l]
    float* sX = sM + R * SMM;          // H*SXS  : 32-col chunk of X
    float* sC = sX + H * SXS;          // H*SCC  : C[i][k] = D[i][k], k<56

    const int tid = threadIdx.x;
    const int wp  = tid >> 5;
    const int ln  = tid & 31;
    const long imgbase = (long)blockIdx.x * (H * H);
    const float* __restrict__ xi = x + imgbase;

    // load U (rows 0..55 of D) and C (cols 0..55 of D)
    for (int idx = tid; idx < R * H; idx += NTHR) {
        int k = idx / H;
        int w = idx - k * H;
        sU[k * SU + w] = g_D[idx];
    }
    for (int idx = tid; idx < H * R; idx += NTHR) {
        int i = idx / R;
        int k = idx - i * R;
        sC[i * SCC + k] = g_D[i * H + k];
    }
    __syncthreads();

    // ---- stage 1: t[h][l] = sum_w X[h][w] * U[l][w] ----
    const int l0 = wp * 7;
    float acc[7][7];
#pragma unroll
    for (int a = 0; a < 7; a++)
#pragma unroll
        for (int b = 0; b < 7; b++) acc[a][b] = 0.f;

#pragma unroll 1
    for (int c = 0; c < 7; c++) {
        const int w0 = c * 32;
#pragma unroll
        for (int p = 0; p < 7; p++) {
            int row = (tid >> 3) + 32 * p;
            int cv  = (tid & 7) * 4;
            float4 v = *reinterpret_cast<const float4*>(&xi[row * H + w0 + cv]);
            *reinterpret_cast<float4*>(&sX[row * SXS + cv]) = v;
        }
        __syncthreads();
#pragma unroll 1
        for (int w4 = 0; w4 < 8; w4++) {
            const int wl = w4 * 4;
            float4 xv[7];
#pragma unroll
            for (int hi = 0; hi < 7; hi++)
                xv[hi] = *reinterpret_cast<const float4*>(&sX[(ln + 32 * hi) * SXS + wl]);
#pragma unroll
            for (int li = 0; li < 7; li++) {
                float4 u = *reinterpret_cast<const float4*>(&sU[(l0 + li) * SU + w0 + wl]);
#pragma unroll
                for (int hi = 0; hi < 7; hi++) {
                    acc[li][hi] += u.x * xv[hi].x;
                    acc[li][hi] += u.y * xv[hi].y;
                    acc[li][hi] += u.z * xv[hi].z;
                    acc[li][hi] += u.w * xv[hi].w;
                }
            }
        }
        __syncthreads();
    }
#pragma unroll
    for (int li = 0; li < 7; li++)
#pragma unroll
        for (int hi = 0; hi < 7; hi++)
            sT[(ln + 32 * hi) * STT + l0 + li] = acc[li][hi];
    __syncthreads();

    // ---- stage 2: M[k][l] = sum_h U[k][h] * t[h][l] ----
    {
        const int k0 = wp * 7;
        float a0[7], a1[7];
#pragma unroll
        for (int ki = 0; ki < 7; ki++) { a0[ki] = 0.f; a1[ki] = 0.f; }
#pragma unroll 1
        for (int h4 = 0; h4 < 56; h4++) {
            const int h = h4 * 4;
            float4 u[7];
#pragma unroll
            for (int ki = 0; ki < 7; ki++)
                u[ki] = *reinterpret_cast<const float4*>(&sU[(k0 + ki) * SU + h]);
            const float* up = reinterpret_cast<const float*>(u);
#pragma unroll
            for (int dh = 0; dh < 4; dh++) {
                float t0 = sT[(h + dh) * STT + ln];
                float t1 = (ln < 24) ? sT[(h + dh) * STT + 32 + ln] : 0.f;
#pragma unroll
                for (int ki = 0; ki < 7; ki++) {
                    float uv = up[ki * 4 + dh];
                    a0[ki] += uv * t0;
                    a1[ki] += uv * t1;
                }
            }
        }
#pragma unroll
        for (int ki = 0; ki < 7; ki++) {
            sM[(k0 + ki) * SMM + ln] = a0[ki];
            if (ln < 24) sM[(k0 + ki) * SMM + 32 + ln] = a1[ki];
        }
    }
    __syncthreads();

    // ---- stage 3: W[i][l] = sum_k C[i][k] * M[k][l]; write -W to g_Z ----
    float* zi = g_Z + (long)blockIdx.x * (H * KE);
#pragma unroll 1
    for (int it = 0; it < 4; it++) {
        const int i0 = wp * 28 + it * 7;
        float a0[7], a1[7];
#pragma unroll
        for (int ii = 0; ii < 7; ii++) { a0[ii] = 0.f; a1[ii] = 0.f; }
#pragma unroll 1
        for (int k4 = 0; k4 < 14; k4++) {
            const int k = k4 * 4;
            float4 u[7];
#pragma unroll
            for (int ii = 0; ii < 7; ii++)
                u[ii] = *reinterpret_cast<const float4*>(&sC[(i0 + ii) * SCC + k]);
            const float* up = reinterpret_cast<const float*>(u);
#pragma unroll
            for (int dk = 0; dk < 4; dk++) {
                float m0 = sM[(k + dk) * SMM + ln];
                float m1 = (ln < 24) ? sM[(k + dk) * SMM + 32 + ln] : 0.f;
#pragma unroll
                for (int ii = 0; ii < 7; ii++) {
                    float uv = up[ii * 4 + dk];
                    a0[ii] += uv * m0;
                    a1[ii] += uv * m1;
                }
            }
        }
#pragma unroll
        for (int ii = 0; ii < 7; ii++) {
            zi[(i0 + ii) * KE + H + ln] = -a0[ii];
            if (ln < 24) zi[(i0 + ii) * KE + H + 32 + ln] = -a1[ii];
        }
    }
}

// ---------------------------------------------------------------- KY
// Y = A X per image (NN GEMM), Y -> g_Z columns 0..223
__global__ __launch_bounds__(NTHR, 2)
void ky_kernel(const float* __restrict__ x) {
    __shared__ float sA[TS * BK];        // A tile, [row][k], stride 28
    __shared__ float sB[BK * TS];        // X tile, [k][col], stride 112

    const int tid = threadIdx.x;
    const int ty = tid >> 4, tx = tid & 15;
    const int i0 = blockIdx.y * TS;
    const int w0 = blockIdx.x * TS;
    const long img = blockIdx.z;
    const float* __restrict__ xi = x + img * (H * H);
    float* zi = g_Z + img * (H * KE);

    float acc[7][7];
#pragma unroll
    for (int p = 0; p < 7; p++)
#pragma unroll
        for (int q = 0; q < 7; q++) acc[p][q] = 0.f;

#pragma unroll 1
    for (int kc = 0; kc < H; kc += BK) {
        for (int idx = tid; idx < TS * 7; idx += NTHR) {
            int row = idx / 7;
            int kv  = (idx - row * 7) * 4;
            float4 v = *reinterpret_cast<const float4*>(&g_E[(i0 + row) * KE + kc + kv]);
            *reinterpret_cast<float4*>(&sA[row * BK + kv]) = v;
        }
        for (int idx = tid; idx < BK * 28; idx += NTHR) {
            int kk = idx / 28;
            int cv = (idx - kk * 28) * 4;
            float4 v = *reinterpret_cast<const float4*>(&xi[(kc + kk) * H + w0 + cv]);
            *reinterpret_cast<float4*>(&sB[kk * TS + cv]) = v;
        }
        __syncthreads();
#pragma unroll
        for (int kk = 0; kk < BK; kk++) {
            float a[7], b[7];
#pragma unroll
            for (int p = 0; p < 7; p++) a[p] = sA[(ty * 7 + p) * BK + kk];
#pragma unroll
            for (int q = 0; q < 7; q++) b[q] = sB[kk * TS + tx * 7 + q];
#pragma unroll
            for (int p = 0; p < 7; p++)
#pragma unroll
                for (int q = 0; q < 7; q++) acc[p][q] += a[p] * b[q];
        }
        __syncthreads();
    }
#pragma unroll
    for (int p = 0; p < 7; p++)
#pragma unroll
        for (int q = 0; q < 7; q++)
            zi[(i0 + ty * 7 + p) * KE + w0 + tx * 7 + q] = acc[p][q];
}

// ---------------------------------------------------------------- KZ
// G = Z E^T (NT GEMM, k=280), out = x * G
#define SKP 29
__global__ __launch_bounds__(NTHR, 2)
void kz_kernel(const float* __restrict__ x, float* __restrict__ out) {
    __shared__ float sZ[TS * SKP];
    __shared__ float sE[TS * SKP];

    const int tid = threadIdx.x;
    const int ty = tid >> 4, tx = tid & 15;
    const int i0 = blockIdx.y * TS;
    const int j0 = blockIdx.x * TS;
    const long img = blockIdx.z;
    const float* __restrict__ xi = x + img * (H * H);
    float* oi = out + img * (H * H);
    const float* zi = g_Z + img * (H * KE);

    float acc[7][7];
#pragma unroll
    for (int p = 0; p < 7; p++)
#pragma unroll
        for (int q = 0; q < 7; q++) acc[p][q] = 0.f;

#pragma unroll 1
    for (int kc = 0; kc < KE; kc += BK) {
        for (int idx = tid; idx < TS * 7; idx += NTHR) {
            int row = idx / 7;
            int kv  = (idx - row * 7) * 4;
            float4 v = *reinterpret_cast<const float4*>(&zi[(i0 + row) * KE + kc + kv]);
            sZ[row * SKP + kv + 0] = v.x;
            sZ[row * SKP + kv + 1] = v.y;
            sZ[row * SKP + kv + 2] = v.z;
            sZ[row * SKP + kv + 3] = v.w;
            float4 e = *reinterpret_cast<const float4*>(&g_E[(j0 + row) * KE + kc + kv]);
            sE[row * SKP + kv + 0] = e.x;
            sE[row * SKP + kv + 1] = e.y;
            sE[row * SKP + kv + 2] = e.z;
            sE[row * SKP + kv + 3] = e.w;
        }
        __syncthreads();
#pragma unroll
        for (int kk = 0; kk < BK; kk++) {
            float a[7], b[7];
#pragma unroll
            for (int p = 0; p < 7; p++) a[p] = sZ[(ty * 7 + p) * SKP + kk];
#pragma unroll
            for (int q = 0; q < 7; q++) b[q] = sE[(tx * 7 + q) * SKP + kk];
#pragma unroll
            for (int p = 0; p < 7; p++)
#pragma unroll
                for (int q = 0; q < 7; q++) acc[p][q] += a[p] * b[q];
        }
        __syncthreads();
    }
#pragma unroll
    for (int p = 0; p < 7; p++) {
        int i = i0 + ty * 7 + p;
#pragma unroll
        for (int q = 0; q < 7; q++) {
            int j = j0 + tx * 7 + q;
            float xv = xi[i * H + j];
            oi[i * H + j] = xv * acc[p][q];
        }
    }
}

// ---------------------------------------------------------------- launch
extern "C" void kernel_launch(void* const* d_in, const int* in_sizes, int n_in,
                              void* d_out, int out_size) {
    const float* x = (const float*)d_in[0];
    float* out = (float*)d_out;
    const int nimg = out_size / (H * H);  // 1536

    init_D_kernel<<<(H * H + 255) / 256, 256>>>();
    init_E_kernel<<<H, 256>>>();

    const size_t smem_kw =
        (size_t)(R * SU + H * STT + R * SMM + H * SXS + H * SCC) * sizeof(float);
    static int cfg_done = 0;
    cudaFuncSetAttribute(kw_kernel, cudaFuncAttributeMaxDynamicSharedMemorySize,
                         (int)smem_kw);
    (void)cfg_done;

    kw_kernel<<<nimg, NTHR, smem_kw>>>(x);

    dim3 grid(2, 2, nimg);
    ky_kernel<<<grid, NTHR>>>(x);
    kz_kernel<<<grid, NTHR>>>(x, out);
}

// round 6
// speedup vs baseline: 1.3787x; 1.3698x over previous
#include <cuda_runtime.h>
#include <cuda_fp16.h>
#include <math.h>
#include <stdint.h>

#define H 224
#define WP 256
#define NIMG 1536
#define ZN (1536ULL * 224 * 256)
#define SAS 144                  // smem row stride in bytes (72 halfs)
#define ARR 18432                // one smem operand array: 128*SAS

__device__ __half g_Dh[H * WP], g_Dl[H * WP];
__device__ __half g_Z1h[ZN], g_Z1l[ZN], g_Z2h[ZN], g_Z2l[ZN];

__global__ void init_D_kernel() {
    int idx = blockIdx.x * blockDim.x + threadIdx.x;
    if (idx >= H * WP) return;
    int k = idx >> 8, i = idx & 255;
    double v = 0.0;
    if (i < H) {
        v = cos(3.14159265358979323846 * (2.0 * i + 1.0) * (double)k / (2.0 * H))
          * sqrt(2.0 / (double)H);
        if (k == 0) v *= 0.70710678118654752440;
    }
    float f = (float)v;
    __half h = __float2half_rn(f);
    g_Dh[idx] = h;
    g_Dl[idx] = __float2half_rn(f - __half2float(h));
}

__device__ __forceinline__ uint32_t smem_u32(const void* p) {
    uint32_t a;
    asm("{ .reg .u64 t; cvta.to.shared.u64 t, %1; cvt.u32.u64 %0, t; }" : "=r"(a) : "l"(p));
    return a;
}
__device__ __forceinline__ void ldsm4(uint32_t* r, uint32_t a) {
    asm volatile("ldmatrix.sync.aligned.m8n8.x4.shared.b16 {%0,%1,%2,%3}, [%4];"
                 : "=r"(r[0]), "=r"(r[1]), "=r"(r[2]), "=r"(r[3]) : "r"(a));
}
__device__ __forceinline__ void ldsm2(uint32_t* r, uint32_t a) {
    asm volatile("ldmatrix.sync.aligned.m8n8.x2.shared.b16 {%0,%1}, [%2];"
                 : "=r"(r[0]), "=r"(r[1]) : "r"(a));
}
__device__ __forceinline__ void mma16816(float* d, const uint32_t* a, const uint32_t* b) {
    asm volatile("mma.sync.aligned.m16n8k16.row.col.f32.f16.f16.f32 "
                 "{%0,%1,%2,%3}, {%4,%5,%6,%7}, {%8,%9}, {%0,%1,%2,%3};"
                 : "+f"(d[0]), "+f"(d[1]), "+f"(d[2]), "+f"(d[3])
                 : "r"(a[0]), "r"(a[1]), "r"(a[2]), "r"(a[3]), "r"(b[0]), "r"(b[1]));
}
__device__ __forceinline__ uint32_t psplit(float f0, float f1, uint32_t& lo) {
    __half h0 = __float2half_rn(f0), h1 = __float2half_rn(f1);
    __half2 lp = __floats2half2_rn(f0 - __half2float(h0), f1 - __half2float(h1));
    lo = *(uint32_t*)&lp;
    __half2 hp; hp.x = h0; hp.y = h1;
    return *(uint32_t*)&hp;
}

// mode 0: Z1 = D.X^T   (B from fp32 x, split on the fly)
// mode 1: Z2 = D.Z1^T, zero rows<56 & cols<56 (mask)
// mode 2: Z1 = D.Z2^T
// mode 3: out = x * (D.Z1^T)
__global__ __launch_bounds__(256, 2)
void gemm_kernel(const float* __restrict__ x, float* __restrict__ fout, int mode) {
    extern __shared__ char sm[];
    const int tid = threadIdx.x, wid = tid >> 5, lane = tid & 31;
    const int img = blockIdx.y;
    const int m0 = (blockIdx.x & 1) * 96, n0 = (blockIdx.x >> 1) * 96;
    const int wm = (wid >> 2) * 64, wn = (wid & 3) * 32;

    const __half *Bh, *Bl;
    __half *Oh, *Ol;
    if (mode == 1)      { Bh = g_Z1h; Bl = g_Z1l; Oh = g_Z2h; Ol = g_Z2l; }
    else if (mode == 2) { Bh = g_Z2h; Bl = g_Z2l; Oh = g_Z1h; Ol = g_Z1l; }
    else if (mode == 3) { Bh = g_Z1h; Bl = g_Z1l; Oh = 0;     Ol = 0;     }
    else                { Bh = 0;     Bl = 0;     Oh = g_Z1h; Ol = g_Z1l; }

    const float* xi = x + (size_t)img * H * H;
    const char* gDh = (const char*)g_Dh;
    const char* gDl = (const char*)g_Dl;
    const char* gBh = (const char*)(Bh + (size_t)img * H * WP);
    const char* gBl = (const char*)(Bl + (size_t)img * H * WP);

    float acc[16][4];
#pragma unroll
    for (int i = 0; i < 16; i++)
#pragma unroll
        for (int q = 0; q < 4; q++) acc[i][q] = 0.f;

    const uint32_t smb = smem_u32(sm);
    // ldmatrix lane addresses
    const uint32_t aab = smb + (uint32_t)(wm + (lane & 15)) * SAS + (lane >> 4) * 16;
    const int lb = lane & 15;
    const uint32_t bab = smb + 2 * ARR + (uint32_t)(wn + (lb & 7)) * SAS + (lb >> 3) * 16;

#pragma unroll 1
    for (int c = 0; c < 4; c++) {
        // ---- load A (D) chunk: rows m0..m0+127, cols 64c..64c+63 (hi & lo) ----
        for (int u = tid; u < 1024; u += 256) {
            int r = u >> 3, j = u & 7;
            size_t gb = ((size_t)(m0 + r) * WP + c * 64) * 2 + (size_t)j * 16;
            uint32_t so = r * SAS + j * 16;
            *(uint4*)(sm + so)       = *(const uint4*)(gDh + gb);
            *(uint4*)(sm + ARR + so) = *(const uint4*)(gDl + gb);
        }
        // ---- load B chunk: rows n0..n0+127 ----
        if (mode == 0) {
            for (int u = tid; u < 2048; u += 256) {
                int r = u >> 4, jj = u & 15;
                int col = c * 64 + jj * 4;
                float4 v = make_float4(0.f, 0.f, 0.f, 0.f);
                if (col < H) v = *(const float4*)(xi + (size_t)(n0 + r) * H + col);
                uint32_t l0, l1;
                uint32_t h0 = psplit(v.x, v.y, l0);
                uint32_t h1 = psplit(v.z, v.w, l1);
                uint32_t so = r * SAS + jj * 8;
                *(uint2*)(sm + 2 * ARR + so) = make_uint2(h0, h1);
                *(uint2*)(sm + 3 * ARR + so) = make_uint2(l0, l1);
            }
        } else {
            for (int u = tid; u < 1024; u += 256) {
                int r = u >> 3, j = u & 7;
                size_t gb = ((size_t)(n0 + r) * WP + c * 64) * 2 + (size_t)j * 16;
                uint32_t so = r * SAS + j * 16;
                *(uint4*)(sm + 2 * ARR + so) = *(const uint4*)(gBh + gb);
                *(uint4*)(sm + 3 * ARR + so) = *(const uint4*)(gBl + gb);
            }
        }
        __syncthreads();

        // ---- compute 4 k-steps of 16 ----
#pragma unroll
        for (int ks = 0; ks < 4; ks++) {
            const uint32_t ko = ks * 32;  // 16 halfs = 32 bytes
            uint32_t bh[4][2], bl[4][2];
#pragma unroll
            for (int j = 0; j < 4; j++) {
                ldsm2(bh[j], bab + j * 8 * SAS + ko);
                ldsm2(bl[j], bab + j * 8 * SAS + ko + ARR);
            }
#pragma unroll
            for (int i = 0; i < 4; i++) {
                uint32_t ah[4], al[4];
                ldsm4(ah, aab + i * 16 * SAS + ko);
                ldsm4(al, aab + i * 16 * SAS + ko + ARR);
#pragma unroll
                for (int j = 0; j < 4; j++) {
                    mma16816(acc[i * 4 + j], ah, bh[j]);
                    mma16816(acc[i * 4 + j], ah, bl[j]);
                    mma16816(acc[i * 4 + j], al, bh[j]);
                }
            }
        }
        __syncthreads();
    }

    // ---- epilogue ----
#pragma unroll
    for (int i = 0; i < 4; i++) {
#pragma unroll
        for (int j = 0; j < 4; j++) {
            float* d = acc[i * 4 + j];
            int m1 = m0 + wm + 16 * i + (lane >> 2);
            int n  = n0 + wn + 8 * j + ((lane & 3) << 1);
            if (mode == 3) {
                const float* xr = xi + (size_t)m1 * H + n;
                float* orow = fout + (size_t)img * H * H + (size_t)m1 * H + n;
                float2 x0 = *(const float2*)xr;
                float2 x1 = *(const float2*)(xr + 8 * H);
                *(float2*)orow = make_float2(x0.x * d[0], x0.y * d[1]);
                *(float2*)(orow + 8 * H) = make_float2(x1.x * d[2], x1.y * d[3]);
            } else {
                float f0 = d[0], f1 = d[1], f2 = d[2], f3 = d[3];
                if (mode == 1 && n < 56) {
                    if (m1 < 56) { f0 = 0.f; f1 = 0.f; }
                    if (m1 + 8 < 56) { f2 = 0.f; f3 = 0.f; }
                }
                uint32_t lo0, lo1;
                uint32_t hi0 = psplit(f0, f1, lo0);
                uint32_t hi1 = psplit(f2, f3, lo1);
                char* oh = (char*)Oh + ((size_t)img * H * WP + (size_t)m1 * WP + n) * 2;
                char* ol = (char*)Ol + ((size_t)img * H * WP + (size_t)m1 * WP + n) * 2;
                *(uint32_t*)oh = hi0;
                *(uint32_t*)ol = lo0;
                *(uint32_t*)(oh + 8 * WP * 2) = hi1;
                *(uint32_t*)(ol + 8 * WP * 2) = lo1;
            }
        }
    }
}

extern "C" void kernel_launch(void* const* d_in, const int* in_sizes, int n_in,
                              void* d_out, int out_size) {
    const float* x = (const float*)d_in[0];
    float* out = (float*)d_out;

    init_D_kernel<<<(H * WP + 255) / 256, 256>>>();

    const int smem = 4 * ARR;  // 73728
    cudaFuncSetAttribute(gemm_kernel, cudaFuncAttributeMaxDynamicSharedMemorySize, smem);

    dim3 g(4, NIMG);
    gemm_kernel<<<g, 256, smem>>>(x, out, 0);
    gemm_kernel<<<g, 256, smem>>>(x, out, 1);
    gemm_kernel<<<g, 256, smem>>>(x, out, 2);
    gemm_kernel<<<g, 256, smem>>>(x, out, 3);
}

// round 8
// speedup vs baseline: 1.7030x; 1.2352x over previous
#include <cuda_runtime.h>
#include <cuda_fp16.h>
#include <math.h>
#include <stdint.h>

#define H 224
#define WPAD 256
#define NIMG 1536
#define ZN (1536ULL * 224 * 256)
#define RS 80            // smem row stride (bytes)
#define ASZ 10240        // one operand array: 128*RS
#define STG 40960        // stage = 4 arrays
#define NC 7             // K chunks of 32

__device__ __half g_Dh[H * WPAD], g_Dl[H * WPAD];
__device__ __half g_Xh[ZN], g_Xl[ZN];
__device__ __half g_Z1h[ZN], g_Z1l[ZN];
__device__ __half g_Z2h[ZN], g_Z2l[ZN];

__global__ void init_D_kernel() {
    int idx = blockIdx.x * blockDim.x + threadIdx.x;
    if (idx >= H * WPAD) return;
    int k = idx >> 8, i = idx & 255;
    double v = 0.0;
    if (i < H) {
        v = cos(3.14159265358979323846 * (2.0 * i + 1.0) * (double)k / (2.0 * H))
          * sqrt(2.0 / (double)H);
        if (k == 0) v *= 0.70710678118654752440;
    }
    float f = (float)v;
    __half h = __float2half_rn(f);
    g_Dh[idx] = h;
    g_Dl[idx] = __float2half_rn(f - __half2float(h));
}

__device__ __forceinline__ uint32_t psplit(float f0, float f1, uint32_t& lo) {
    __half h0 = __float2half_rn(f0), h1 = __float2half_rn(f1);
    __half2 lp = __floats2half2_rn(f0 - __half2float(h0), f1 - __half2float(h1));
    lo = *(uint32_t*)&lp;
    __half2 hp; hp.x = h0; hp.y = h1;
    return *(uint32_t*)&hp;
}

// split x (fp32) into g_Xh/g_Xl, padded row stride 256
__global__ __launch_bounds__(256)
void kxc_kernel(const float* __restrict__ x) {
    size_t idx4 = ((size_t)blockIdx.x * 256 + threadIdx.x) * 4;
    if (idx4 >= (size_t)NIMG * H * H) return;
    size_t img = idx4 / (H * H);
    int rem = (int)(idx4 - img * (H * H));
    int h = rem / H, w = rem - h * H;
    float4 v = *(const float4*)(x + idx4);
    uint32_t l0, l1;
    uint32_t h0 = psplit(v.x, v.y, l0);
    uint32_t h1 = psplit(v.z, v.w, l1);
    size_t off = (img * H + h) * WPAD + w;
    *(uint2*)(g_Xh + off) = make_uint2(h0, h1);
    *(uint2*)(g_Xl + off) = make_uint2(l0, l1);
}

__device__ __forceinline__ uint32_t smem_u32(const void* p) {
    uint32_t a;
    asm("{ .reg .u64 t; cvta.to.shared.u64 t, %1; cvt.u32.u64 %0, t; }" : "=r"(a) : "l"(p));
    return a;
}
__device__ __forceinline__ void ldsm4(uint32_t* r, uint32_t a) {
    asm volatile("ldmatrix.sync.aligned.m8n8.x4.shared.b16 {%0,%1,%2,%3}, [%4];"
                 : "=r"(r[0]), "=r"(r[1]), "=r"(r[2]), "=r"(r[3]) : "r"(a));
}
__device__ __forceinline__ void ldsm2(uint32_t* r, uint32_t a) {
    asm volatile("ldmatrix.sync.aligned.m8n8.x2.shared.b16 {%0,%1}, [%2];"
                 : "=r"(r[0]), "=r"(r[1]) : "r"(a));
}
__device__ __forceinline__ void mma16816(float* d, const uint32_t* a, const uint32_t* b) {
    asm volatile("mma.sync.aligned.m16n8k16.row.col.f32.f16.f16.f32 "
                 "{%0,%1,%2,%3}, {%4,%5,%6,%7}, {%8,%9}, {%0,%1,%2,%3};"
                 : "+f"(d[0]), "+f"(d[1]), "+f"(d[2]), "+f"(d[3])
                 : "r"(a[0]), "r"(a[1]), "r"(a[2]), "r"(a[3]), "r"(b[0]), "r"(b[1]));
}
__device__ __forceinline__ void cpa16(uint32_t d, const void* s) {
    asm volatile("cp.async.cg.shared.global [%0], [%1], 16;" :: "r"(d), "l"(s));
}

// mode 0: Z1 = D.X^T; 1: Z2 = D.Z1^T (mask); 2: Z1 = D.Z2^T; 3: out = x*(D.Z1^T)
__global__ __launch_bounds__(256, 2)
void gemm_kernel(const float* __restrict__ x, float* __restrict__ fout, int mode) {
    extern __shared__ char sm[];
    const int tid = threadIdx.x, wid = tid >> 5, lane = tid & 31;
    const int img = blockIdx.y;
    const int m0 = (blockIdx.x & 1) * 96, n0 = (blockIdx.x >> 1) * 96;
    const int wm = (wid >> 2) * 64, wn = (wid & 3) * 32;

    const __half *Bh, *Bl;
    __half *Oh, *Ol;
    if (mode == 1)      { Bh = g_Z1h; Bl = g_Z1l; Oh = g_Z2h; Ol = g_Z2l; }
    else if (mode == 2) { Bh = g_Z2h; Bl = g_Z2l; Oh = g_Z1h; Ol = g_Z1l; }
    else if (mode == 3) { Bh = g_Z1h; Bl = g_Z1l; Oh = 0;     Ol = 0;     }
    else                { Bh = g_Xh;  Bl = g_Xl;  Oh = g_Z1h; Ol = g_Z1l; }

    const float* xi = x + (size_t)img * H * H;
    const char* gDh = (const char*)g_Dh;
    const char* gDl = (const char*)g_Dl;
    const char* gBh = (const char*)(Bh + (size_t)img * H * WPAD);
    const char* gBl = (const char*)(Bl + (size_t)img * H * WPAD);

    float acc[16][4];
#pragma unroll
    for (int i = 0; i < 16; i++)
#pragma unroll
        for (int q = 0; q < 4; q++) acc[i][q] = 0.f;

    const uint32_t smb = smem_u32(sm);
    const uint32_t aab = smb + (uint32_t)(wm + (lane & 15)) * RS + (lane >> 4) * 16;
    const int lb = lane & 15;
    const uint32_t bab = smb + 2 * ASZ + (uint32_t)(wn + (lb & 7)) * RS + ((lb >> 3) & 1) * 16;

    // chunk loader: c = K chunk (32 halfs = 64 bytes in 512B rows), stg in {0,1}
    const int r0 = tid >> 2, j0 = (tid & 3) * 16;   // each thread: rows r0, r0+64
#pragma unroll 1
    for (int c = 0; c <= NC; c++) {
        if (c < NC) {
            const uint32_t sb = smb + (c & 1) * STG;
            const size_t ko = (size_t)c * 64;
#pragma unroll
            for (int p = 0; p < 2; p++) {
                int r = r0 + p * 64;
                uint32_t so = r * RS + j0;
                size_t ga = (size_t)(m0 + r) * 512 + ko + j0;
                size_t gb = (size_t)(n0 + r) * 512 + ko + j0;
                cpa16(sb + so,            gDh + ga);
                cpa16(sb + ASZ + so,      gDl + ga);
                cpa16(sb + 2 * ASZ + so,  gBh + gb);
                cpa16(sb + 3 * ASZ + so,  gBl + gb);
            }
            asm volatile("cp.async.commit_group;" ::: "memory");
        }
        if (c == 0) continue;
        // compute chunk c-1
        if (c < NC) asm volatile("cp.async.wait_group 1;" ::: "memory");
        else        asm volatile("cp.async.wait_group 0;" ::: "memory");
        __syncthreads();
        const uint32_t sb = smb + ((c - 1) & 1) * STG;
        const uint32_t ab = aab + ((c - 1) & 1) * STG - 0;
        const uint32_t bb = bab + ((c - 1) & 1) * STG;
#pragma unroll
        for (int ks = 0; ks < 2; ks++) {
            const uint32_t ko = ks * 32;
            uint32_t bh[4][2], bl[4][2];
#pragma unroll
            for (int j = 0; j < 4; j++) {
                ldsm2(bh[j], bb + j * 8 * RS + ko);
                ldsm2(bl[j], bb + j * 8 * RS + ko + ASZ);
            }
#pragma unroll
            for (int i = 0; i < 4; i++) {
                uint32_t ah[4], al[4];
                ldsm4(ah, ab + i * 16 * RS + ko);
                ldsm4(al, ab + i * 16 * RS + ko + ASZ);
#pragma unroll
                for (int j = 0; j < 4; j++) {
                    mma16816(acc[i * 4 + j], ah, bh[j]);
                    mma16816(acc[i * 4 + j], ah, bl[j]);
                    mma16816(acc[i * 4 + j], al, bh[j]);
                }
            }
        }
        __syncthreads();
    }

    // ---- epilogue ----
#pragma unroll
    for (int i = 0; i < 4; i++) {
#pragma unroll
        for (int j = 0; j < 4; j++) {
            float* d = acc[i * 4 + j];
            int m1 = m0 + wm + 16 * i + (lane >> 2);
            int n  = n0 + wn + 8 * j + ((lane & 3) << 1);
            if (mode == 3) {
                const float* xr = xi + (size_t)m1 * H + n;
                float* orow = fout + (size_t)img * H * H + (size_t)m1 * H + n;
                float2 x0 = *(const float2*)xr;
                float2 x1 = *(const float2*)(xr + 8 * H);
                *(float2*)orow = make_float2(x0.x * d[0], x0.y * d[1]);
                *(float2*)(orow + 8 * H) = make_float2(x1.x * d[2], x1.y * d[3]);
            } else {
                float f0 = d[0], f1 = d[1], f2 = d[2], f3 = d[3];
                if (mode == 1 && n < 56) {
                    if (m1 < 56) { f0 = 0.f; f1 = 0.f; }
                    if (m1 + 8 < 56) { f2 = 0.f; f3 = 0.f; }
                }
                uint32_t lo0, lo1;
                uint32_t hi0 = psplit(f0, f1, lo0);
                uint32_t hi1 = psplit(f2, f3, lo1);
                char* oh = (char*)Oh + ((size_t)img * H * WPAD + (size_t)m1 * WPAD + n) * 2;
                char* ol = (char*)Ol + ((size_t)img * H * WPAD + (size_t)m1 * WPAD + n) * 2;
                *(uint32_t*)oh = hi0;
                *(uint32_t*)ol = lo0;
                *(uint32_t*)(oh + 8 * WPAD * 2) = hi1;
                *(uint32_t*)(ol + 8 * WPAD * 2) = lo1;
            }
        }
    }
}

extern "C" void kernel_launch(void* const* d_in, const int* in_sizes, int n_in,
                              void* d_out, int out_size) {
    const float* x = (const float*)d_in[0];
    float* out = (float*)d_out;

    init_D_kernel<<<(H * WPAD + 255) / 256, 256>>>();
    kxc_kernel<<<(int)(((size_t)NIMG * H * H / 4 + 255) / 256), 256>>>(x);

    const int smem = 2 * STG;  // 81920
    cudaFuncSetAttribute(gemm_kernel, cudaFuncAttributeMaxDynamicSharedMemorySize, smem);

    dim3 g(4, NIMG);
    gemm_kernel<<<g, 256, smem>>>(x, out, 0);
    gemm_kernel<<<g, 256, smem>>>(x, out, 1);
    gemm_kernel<<<g, 256, smem>>>(x, out, 2);
    gemm_kernel<<<g, 256, smem>>>(x, out, 3);
}